// round 2
// baseline (speedup 1.0000x reference)
#include <cuda_runtime.h>
#include <cuda_bf16.h>

typedef unsigned long long ull;

#define GMM_M   64
#define GMM_D   16
#define GMM_KP  8      // 16 dims = 8 f32x2 pairs
#define TPB     128    // threads per block (main kernel)
#define PPT     4      // points per thread
#define PPB     (TPB*PPT)

// Interleaved params: g_P[m*8+k] = {A_{2k}, A_{2k+1}, B_{2k}, B_{2k+1}}
// where A = -0.5*prec, B = prec*mu.
__device__ float4 g_P[GMM_M * GMM_KP];
__device__ float  g_C[GMM_M];        // log(w*(2pi)^-8*|S|^-1/2) - 0.5*sum(prec*mu^2)
__device__ float  g_part[8192];      // per-block partial log-like sums

// ---------- packed f32x2 helpers ----------
__device__ __forceinline__ ull pk2(float lo, float hi) {
    ull r; asm("mov.b64 %0, {%1, %2};" : "=l"(r) : "f"(lo), "f"(hi)); return r;
}
__device__ __forceinline__ void upk2(ull v, float &lo, float &hi) {
    asm("mov.b64 {%0, %1}, %2;" : "=f"(lo), "=f"(hi) : "l"(v));
}
__device__ __forceinline__ ull fma2(ull a, ull b, ull c) {
    ull r; asm("fma.rn.f32x2 %0, %1, %2, %3;" : "=l"(r) : "l"(a), "l"(b), "l"(c)); return r;
}

// ---------- kernel 1: parameter precompute, thread per (m,d) ----------
__global__ void __launch_bounds__(1024)
gmm_precompute(const float* __restrict__ wghts,
               const float* __restrict__ means,
               const float* __restrict__ dcovs) {
    __shared__ float sAf[GMM_M][GMM_D];
    __shared__ float sBf[GMM_M][GMM_D];
    const int tid = threadIdx.x;
    const int m = tid >> 4;
    const int d = tid & 15;

    const float dc   = dcovs[m * GMM_D + d];
    const float mu   = means[m * GMM_D + d];
    const float prec = 1.0f / dc;
    sAf[m][d] = -0.5f * prec;
    sBf[m][d] = prec * mu;

    // per-(m,d) contribution to C, reduced over 16-lane segments
    float cpart = -0.5f * prec * mu * mu - 0.5f * __logf(dc);
    #pragma unroll
    for (int o = 8; o > 0; o >>= 1)
        cpart += __shfl_down_sync(0xffffffffu, cpart, o, 16);
    if (d == 0)
        g_C[m] = cpart + __logf(wghts[m]) - 8.0f * __logf(6.283185307f);

    __syncthreads();
    if (tid < GMM_M * GMM_KP) {
        const int pm = tid >> 3;
        const int k  = tid & 7;
        g_P[tid] = make_float4(sAf[pm][2*k], sAf[pm][2*k+1],
                               sBf[pm][2*k], sBf[pm][2*k+1]);
    }
}

// ---------- kernel 2: main GMM E-step ----------
__global__ void __launch_bounds__(TPB)
gmm_main(const float* __restrict__ data,
         const float* __restrict__ means,
         float* __restrict__ out,   // out[0]=loglike (finalize), out[1..]=e_means
         int T) {
    __shared__ ulonglong2 sP[GMM_M * GMM_KP];   // {A pair, B pair} per (m,k)
    __shared__ ulonglong2 sMu[GMM_M * 4];       // mu pairs, 4 x 16B per mixture
    __shared__ float      sC[GMM_M];
    __shared__ float      sRed[TPB];

    const int tid = threadIdx.x;
    {
        const float4* gp = (const float4*)g_P;
        float4*       dp = (float4*)sP;
        for (int i = tid; i < GMM_M * GMM_KP; i += TPB) dp[i] = gp[i];
        const float4* gm = (const float4*)means;
        float4*       dm = (float4*)sMu;
        for (int i = tid; i < GMM_M * 4; i += TPB) dm[i] = gm[i];
        if (tid < GMM_M) sC[tid] = g_C[tid];
    }
    __syncthreads();

    const int base = blockIdx.x * PPB;
    int  t[PPT];
    bool v[PPT];
    #pragma unroll
    for (int j = 0; j < PPT; j++) { t[j] = base + tid + j * TPB; v[j] = (t[j] < T); }

    ull  x[PPT][GMM_KP], num[PPT][GMM_KP];
    float like[PPT];

    #pragma unroll
    for (int j = 0; j < PPT; j++) {
        like[j] = 0.0f;
        if (v[j]) {
            const ull* dp = (const ull*)(data + (size_t)t[j] * GMM_D);
            #pragma unroll
            for (int k = 0; k < GMM_KP; k++) x[j][k] = dp[k];
        } else {
            #pragma unroll
            for (int k = 0; k < GMM_KP; k++) x[j][k] = 0ULL;
        }
        #pragma unroll
        for (int k = 0; k < GMM_KP; k++) num[j][k] = 0ULL;
    }

    #pragma unroll 2
    for (int m = 0; m < GMM_M; m++) {
        ull acc[PPT];
        #pragma unroll
        for (int j = 0; j < PPT; j++) acc[j] = 0ULL;

        // Mahalanobis + linear term: acc += (A*x + B) * x  (per f32x2 pair)
        #pragma unroll
        for (int k = 0; k < GMM_KP; k++) {
            const ulonglong2 ab = sP[m * GMM_KP + k];   // LDS.128 broadcast
            #pragma unroll
            for (int j = 0; j < PPT; j++) {
                const ull tt = fma2(ab.x, x[j][k], ab.y);
                acc[j] = fma2(tt, x[j][k], acc[j]);
            }
        }

        // mixture means for numerator (4 x LDS.128)
        ull mur[GMM_KP];
        #pragma unroll
        for (int kk = 0; kk < 4; kk++) {
            const ulonglong2 mm = sMu[m * 4 + kk];
            mur[2 * kk]     = mm.x;
            mur[2 * kk + 1] = mm.y;
        }

        const float c = sC[m];
        #pragma unroll
        for (int j = 0; j < PPT; j++) {
            float lo, hi;
            upk2(acc[j], lo, hi);
            const float p = __expf(c + lo + hi);
            like[j] += p;
            const ull pb = pk2(p, p);
            #pragma unroll
            for (int k = 0; k < GMM_KP; k++)
                num[j][k] = fma2(pb, mur[k], num[j][k]);
        }
    }

    float ll = 0.0f;
    #pragma unroll
    for (int j = 0; j < PPT; j++) {
        if (v[j]) {
            const float inv = __fdividef(1.0f, like[j]);
            float* oe = out + 1 + (size_t)t[j] * GMM_D;
            #pragma unroll
            for (int k = 0; k < GMM_KP; k++) {
                float f0, f1;
                upk2(num[j][k], f0, f1);
                oe[2 * k]     = f0 * inv;
                oe[2 * k + 1] = f1 * inv;
            }
            ll += __logf(like[j]);
        }
    }

    // deterministic fixed-tree block reduction of log-likes
    sRed[tid] = ll;
    __syncthreads();
    #pragma unroll
    for (int s = TPB / 2; s > 0; s >>= 1) {
        if (tid < s) sRed[tid] += sRed[tid + s];
        __syncthreads();
    }
    if (tid == 0) g_part[blockIdx.x] = sRed[0];
}

// ---------- kernel 3: finalize log-like mean (deterministic tree) ----------
__global__ void __launch_bounds__(1024)
gmm_finalize(float* __restrict__ out, int nblocks, float invT) {
    __shared__ float s[1024];
    const int tid = threadIdx.x;
    float acc = 0.0f;
    for (int i = tid; i < nblocks; i += 1024) acc += g_part[i];
    s[tid] = acc;
    __syncthreads();
    #pragma unroll
    for (int st = 512; st > 0; st >>= 1) {
        if (tid < st) s[tid] += s[tid + st];
        __syncthreads();
    }
    if (tid == 0) out[0] = s[0] * invT;
}

extern "C" void kernel_launch(void* const* d_in, const int* in_sizes, int n_in,
                              void* d_out, int out_size) {
    const float* data  = (const float*)d_in[0];
    const float* wghts = (const float*)d_in[1];
    const float* means = (const float*)d_in[2];
    const float* dcovs = (const float*)d_in[3];
    float* out = (float*)d_out;

    const int T = in_sizes[0] / GMM_D;
    const int nblocks = (T + PPB - 1) / PPB;

    gmm_precompute<<<1, 1024>>>(wghts, means, dcovs);
    gmm_main<<<nblocks, TPB>>>(data, means, out, T);
    gmm_finalize<<<1, 1024>>>(out, nblocks, 1.0f / (float)T);
}

// round 3
// speedup vs baseline: 1.1030x; 1.1030x over previous
#include <cuda_runtime.h>
#include <cuda_bf16.h>

typedef unsigned long long ull;

#define GMM_M   64
#define GMM_D   16
#define GMM_KP  8      // 16 dims = 8 f32x2 pairs
#define TPB     128    // threads per block (main kernel)
#define PPT     2      // points per thread
#define PPB     (TPB*PPT)

// Interleaved params: g_P[m*8+k] = {A_{2k}, A_{2k+1}, B_{2k}, B_{2k+1}}
// where A = -0.5*prec, B = prec*mu.
__device__ float4   g_P[GMM_M * GMM_KP];
__device__ float    g_C[GMM_M];      // log(w*(2pi)^-8*|S|^-1/2) - 0.5*sum(prec*mu^2)
__device__ float    g_part[8192];    // per-block partial log-like sums
__device__ unsigned g_count = 0;     // last-block ticket (self-resetting)

// ---------- packed f32x2 helpers ----------
__device__ __forceinline__ ull pk2(float lo, float hi) {
    ull r; asm("mov.b64 %0, {%1, %2};" : "=l"(r) : "f"(lo), "f"(hi)); return r;
}
__device__ __forceinline__ void upk2(ull v, float &lo, float &hi) {
    asm("mov.b64 {%0, %1}, %2;" : "=f"(lo), "=f"(hi) : "l"(v));
}
__device__ __forceinline__ ull fma2(ull a, ull b, ull c) {
    ull r; asm("fma.rn.f32x2 %0, %1, %2, %3;" : "=l"(r) : "l"(a), "l"(b), "l"(c)); return r;
}

// ---------- kernel 1: parameter precompute, thread per (m,d) ----------
__global__ void __launch_bounds__(1024)
gmm_precompute(const float* __restrict__ wghts,
               const float* __restrict__ means,
               const float* __restrict__ dcovs) {
    __shared__ float sAf[GMM_M][GMM_D];
    __shared__ float sBf[GMM_M][GMM_D];
    const int tid = threadIdx.x;
    const int m = tid >> 4;
    const int d = tid & 15;

    const float dc   = dcovs[m * GMM_D + d];
    const float mu   = means[m * GMM_D + d];
    const float prec = 1.0f / dc;
    sAf[m][d] = -0.5f * prec;
    sBf[m][d] = prec * mu;

    float cpart = -0.5f * prec * mu * mu - 0.5f * __logf(dc);
    #pragma unroll
    for (int o = 8; o > 0; o >>= 1)
        cpart += __shfl_down_sync(0xffffffffu, cpart, o, 16);
    if (d == 0)
        g_C[m] = cpart + __logf(wghts[m]) - 8.0f * __logf(6.283185307f);

    __syncthreads();
    if (tid < GMM_M * GMM_KP) {
        const int pm = tid >> 3;
        const int k  = tid & 7;
        g_P[tid] = make_float4(sAf[pm][2*k], sAf[pm][2*k+1],
                               sBf[pm][2*k], sBf[pm][2*k+1]);
    }
}

// ---------- kernel 2: main GMM E-step + fused finalize ----------
__global__ void __launch_bounds__(TPB, 4)
gmm_main(const float* __restrict__ data,
         const float* __restrict__ means,
         float* __restrict__ out,   // out[0]=loglike, out[1..]=e_means
         int T, int nblocks, float invT) {
    __shared__ ulonglong2 sP[GMM_M * GMM_KP];   // {A pair, B pair} per (m,k)
    __shared__ ulonglong2 sMu[GMM_M * 4];       // mu pairs, 4 x 16B per mixture
    __shared__ float      sC[GMM_M];
    __shared__ float      sRed[TPB];
    __shared__ bool       sLast;

    const int tid = threadIdx.x;
    {
        const float4* gp = (const float4*)g_P;
        float4*       dp = (float4*)sP;
        for (int i = tid; i < GMM_M * GMM_KP; i += TPB) dp[i] = gp[i];
        const float4* gm = (const float4*)means;
        float4*       dm = (float4*)sMu;
        for (int i = tid; i < GMM_M * 4; i += TPB) dm[i] = gm[i];
        if (tid < GMM_M) sC[tid] = g_C[tid];
    }
    __syncthreads();

    const int base = blockIdx.x * PPB;
    int  t[PPT];
    bool v[PPT];
    #pragma unroll
    for (int j = 0; j < PPT; j++) { t[j] = base + tid + j * TPB; v[j] = (t[j] < T); }

    ull  x[PPT][GMM_KP], num[PPT][GMM_KP];
    float like[PPT];

    #pragma unroll
    for (int j = 0; j < PPT; j++) {
        like[j] = 0.0f;
        if (v[j]) {
            const ull* dp = (const ull*)(data + (size_t)t[j] * GMM_D);
            #pragma unroll
            for (int k = 0; k < GMM_KP; k++) x[j][k] = dp[k];
        } else {
            #pragma unroll
            for (int k = 0; k < GMM_KP; k++) x[j][k] = 0ULL;
        }
        #pragma unroll
        for (int k = 0; k < GMM_KP; k++) num[j][k] = 0ULL;
    }

    #pragma unroll 1
    for (int m = 0; m < GMM_M; m++) {
        ull acc[PPT];
        #pragma unroll
        for (int j = 0; j < PPT; j++) acc[j] = 0ULL;

        // acc += (A*x + B) * x   per f32x2 pair
        #pragma unroll
        for (int k = 0; k < GMM_KP; k++) {
            const ulonglong2 ab = sP[m * GMM_KP + k];   // LDS.128 broadcast
            #pragma unroll
            for (int j = 0; j < PPT; j++) {
                const ull tt = fma2(ab.x, x[j][k], ab.y);
                acc[j] = fma2(tt, x[j][k], acc[j]);
            }
        }

        const float c = sC[m];
        float p[PPT];
        #pragma unroll
        for (int j = 0; j < PPT; j++) {
            float lo, hi;
            upk2(acc[j], lo, hi);
            p[j] = __expf(c + lo + hi);
            like[j] += p[j];
        }

        // num += p * mu   (mu pairs via LDS.128 broadcast)
        #pragma unroll
        for (int kk = 0; kk < 4; kk++) {
            const ulonglong2 mm = sMu[m * 4 + kk];
            #pragma unroll
            for (int j = 0; j < PPT; j++) {
                const ull pb = pk2(p[j], p[j]);
                num[j][2*kk]   = fma2(pb, mm.x, num[j][2*kk]);
                num[j][2*kk+1] = fma2(pb, mm.y, num[j][2*kk+1]);
            }
        }
    }

    float ll = 0.0f;
    #pragma unroll
    for (int j = 0; j < PPT; j++) {
        if (v[j]) {
            const float inv = __fdividef(1.0f, like[j]);
            float* oe = out + 1 + (size_t)t[j] * GMM_D;
            #pragma unroll
            for (int k = 0; k < GMM_KP; k++) {
                float f0, f1;
                upk2(num[j][k], f0, f1);
                oe[2 * k]     = f0 * inv;
                oe[2 * k + 1] = f1 * inv;
            }
            ll += __logf(like[j]);
        }
    }

    // deterministic fixed-tree block reduction of log-likes
    sRed[tid] = ll;
    __syncthreads();
    #pragma unroll
    for (int s = TPB / 2; s > 0; s >>= 1) {
        if (tid < s) sRed[tid] += sRed[tid + s];
        __syncthreads();
    }
    if (tid == 0) {
        g_part[blockIdx.x] = sRed[0];
        __threadfence();
        unsigned old = atomicAdd(&g_count, 1u);
        sLast = (old == (unsigned)(nblocks - 1));
    }
    __syncthreads();

    // last block finalizes the mean log-likelihood (deterministic fixed order)
    if (sLast) {
        __threadfence();
        float acc2 = 0.0f;
        for (int i = tid; i < nblocks; i += TPB) acc2 += g_part[i];
        sRed[tid] = acc2;
        __syncthreads();
        #pragma unroll
        for (int s = TPB / 2; s > 0; s >>= 1) {
            if (tid < s) sRed[tid] += sRed[tid + s];
            __syncthreads();
        }
        if (tid == 0) {
            out[0] = sRed[0] * invT;
            g_count = 0;   // reset for next graph replay
        }
    }
}

extern "C" void kernel_launch(void* const* d_in, const int* in_sizes, int n_in,
                              void* d_out, int out_size) {
    const float* data  = (const float*)d_in[0];
    const float* wghts = (const float*)d_in[1];
    const float* means = (const float*)d_in[2];
    const float* dcovs = (const float*)d_in[3];
    float* out = (float*)d_out;

    const int T = in_sizes[0] / GMM_D;
    const int nblocks = (T + PPB - 1) / PPB;

    gmm_precompute<<<1, 1024>>>(wghts, means, dcovs);
    gmm_main<<<nblocks, TPB>>>(data, means, out, T, nblocks, 1.0f / (float)T);
}

// round 4
// speedup vs baseline: 1.1439x; 1.0371x over previous
#include <cuda_runtime.h>
#include <cuda_bf16.h>

typedef unsigned long long ull;

#define GMM_M   64
#define GMM_D   16
#define GMM_KP  8      // 16 dims = 8 f32x2 pairs
#define TPB     128
#define PPT     2
#define PPB     (TPB*PPT)
#define NBLK    740    // 148 SMs x 5 blocks

__device__ float4   g_P[GMM_M * GMM_KP];  // {A2k,A2k+1,B2k,B2k+1}, log2e-folded
__device__ float    g_C[GMM_M];           // log2e-folded constant
__device__ float    g_part[NBLK];
__device__ unsigned g_count = 0;

__device__ __forceinline__ ull pk2(float lo, float hi) {
    ull r; asm("mov.b64 %0, {%1, %2};" : "=l"(r) : "f"(lo), "f"(hi)); return r;
}
__device__ __forceinline__ void upk2(ull v, float &lo, float &hi) {
    asm("mov.b64 {%0, %1}, %2;" : "=f"(lo), "=f"(hi) : "l"(v));
}
__device__ __forceinline__ ull fma2(ull a, ull b, ull c) {
    ull r; asm("fma.rn.f32x2 %0, %1, %2, %3;" : "=l"(r) : "l"(a), "l"(b), "l"(c)); return r;
}
__device__ __forceinline__ float ex2f(float x) {
    float r; asm("ex2.approx.f32 %0, %1;" : "=f"(r) : "f"(x)); return r;
}

// ---------- kernel 1: parameter precompute (log2e folded) ----------
__global__ void __launch_bounds__(1024)
gmm_precompute(const float* __restrict__ wghts,
               const float* __restrict__ means,
               const float* __restrict__ dcovs) {
    __shared__ float sAf[GMM_M][GMM_D];
    __shared__ float sBf[GMM_M][GMM_D];
    const int tid = threadIdx.x;
    const int m = tid >> 4;
    const int d = tid & 15;
    const float LOG2E = 1.4426950408889634f;

    const float dc   = dcovs[m * GMM_D + d];
    const float mu   = means[m * GMM_D + d];
    const float prec = 1.0f / dc;
    sAf[m][d] = -0.5f * prec * LOG2E;
    sBf[m][d] = prec * mu * LOG2E;

    float cpart = (-0.5f * prec * mu * mu - 0.5f * __logf(dc)) * LOG2E;
    #pragma unroll
    for (int o = 8; o > 0; o >>= 1)
        cpart += __shfl_down_sync(0xffffffffu, cpart, o, 16);
    if (d == 0)
        g_C[m] = cpart + (__logf(wghts[m]) - 8.0f * __logf(6.283185307f)) * LOG2E;

    __syncthreads();
    if (tid < GMM_M * GMM_KP) {
        const int pm = tid >> 3;
        const int k  = tid & 7;
        g_P[tid] = make_float4(sAf[pm][2*k], sAf[pm][2*k+1],
                               sBf[pm][2*k], sBf[pm][2*k+1]);
    }
}

// ---------- kernel 2: main GMM E-step (block-stride tiles) + fused finalize ----------
__global__ void __launch_bounds__(TPB, 5)
gmm_main(const float* __restrict__ data,
         const float* __restrict__ means,
         float* __restrict__ out,
         int T, int ntiles, float invT) {
    __shared__ ulonglong2 sP[GMM_M * GMM_KP];
    __shared__ ulonglong2 sMu[GMM_M * 4];
    __shared__ float      sC[GMM_M];
    __shared__ float      sStage[TPB * 17];   // pitch-17 transpose buffer
    __shared__ float      sRed[TPB];
    __shared__ bool       sLast;

    const int tid = threadIdx.x;
    {
        const float4* gp = (const float4*)g_P;
        float4*       dp = (float4*)sP;
        for (int i = tid; i < GMM_M * GMM_KP; i += TPB) dp[i] = gp[i];
        const float4* gm = (const float4*)means;
        float4*       dm = (float4*)sMu;
        for (int i = tid; i < GMM_M * 4; i += TPB) dm[i] = gm[i];
        if (tid < GMM_M) sC[tid] = g_C[tid];
    }
    __syncthreads();

    float llsum = 0.0f;

    for (int tile = blockIdx.x; tile < ntiles; tile += gridDim.x) {
        const int base = tile * PPB;

        ull x[PPT][GMM_KP], num[PPT][GMM_KP];
        float like[PPT];

        #pragma unroll
        for (int j = 0; j < PPT; j++) {
            like[j] = 0.0f;
            const int t = base + tid + j * TPB;
            if (t < T) {
                const float4* dp4 = (const float4*)(data + (size_t)t * GMM_D);
                #pragma unroll
                for (int q = 0; q < 4; q++) {
                    const float4 f = dp4[q];
                    x[j][2*q]   = pk2(f.x, f.y);
                    x[j][2*q+1] = pk2(f.z, f.w);
                }
            } else {
                #pragma unroll
                for (int k = 0; k < GMM_KP; k++) x[j][k] = 0ULL;
            }
            #pragma unroll
            for (int k = 0; k < GMM_KP; k++) num[j][k] = 0ULL;
        }

        #pragma unroll 2
        for (int m = 0; m < GMM_M; m++) {
            ull acc[PPT];
            #pragma unroll
            for (int j = 0; j < PPT; j++) acc[j] = 0ULL;

            #pragma unroll
            for (int k = 0; k < GMM_KP; k++) {
                const ulonglong2 ab = sP[m * GMM_KP + k];
                #pragma unroll
                for (int j = 0; j < PPT; j++) {
                    const ull tt = fma2(ab.x, x[j][k], ab.y);
                    acc[j] = fma2(tt, x[j][k], acc[j]);
                }
            }

            const float c = sC[m];
            ull pb[PPT];
            #pragma unroll
            for (int j = 0; j < PPT; j++) {
                float lo, hi;
                upk2(acc[j], lo, hi);
                const float p = ex2f(c + lo + hi);
                like[j] += p;
                pb[j] = pk2(p, p);
            }

            #pragma unroll
            for (int kk = 0; kk < 4; kk++) {
                const ulonglong2 mm = sMu[m * 4 + kk];
                #pragma unroll
                for (int j = 0; j < PPT; j++) {
                    num[j][2*kk]   = fma2(pb[j], mm.x, num[j][2*kk]);
                    num[j][2*kk+1] = fma2(pb[j], mm.y, num[j][2*kk+1]);
                }
            }
        }

        // epilogue: SMEM transpose -> coalesced STG.32 (out+1 is only 4B-aligned)
        #pragma unroll
        for (int j = 0; j < PPT; j++) {
            const int tj = base + tid + j * TPB;
            const bool valid = (tj < T);
            const float inv = valid ? __fdividef(1.0f, like[j]) : 0.0f;
            if (valid) llsum += __logf(like[j]);

            #pragma unroll
            for (int k = 0; k < GMM_KP; k++) {
                float f0, f1;
                upk2(num[j][k], f0, f1);
                sStage[tid * 17 + 2*k]     = f0 * inv;
                sStage[tid * 17 + 2*k + 1] = f1 * inv;
            }
            __syncthreads();

            float* op = out + 1 + (size_t)(base + j * TPB) * GMM_D;
            const int limit = min(TPB, T - (base + j * TPB)) * GMM_D;
            for (int i = tid; i < limit; i += TPB)
                op[i] = sStage[(i >> 4) * 17 + (i & 15)];
            __syncthreads();
        }
    }

    // deterministic block reduction of log-likes
    sRed[tid] = llsum;
    __syncthreads();
    #pragma unroll
    for (int s = TPB / 2; s > 0; s >>= 1) {
        if (tid < s) sRed[tid] += sRed[tid + s];
        __syncthreads();
    }
    if (tid == 0) {
        g_part[blockIdx.x] = sRed[0];
        __threadfence();
        unsigned old = atomicAdd(&g_count, 1u);
        sLast = (old == (unsigned)(gridDim.x - 1));
    }
    __syncthreads();

    if (sLast) {
        __threadfence();
        float acc2 = 0.0f;
        for (int i = tid; i < (int)gridDim.x; i += TPB) acc2 += g_part[i];
        sRed[tid] = acc2;
        __syncthreads();
        #pragma unroll
        for (int s = TPB / 2; s > 0; s >>= 1) {
            if (tid < s) sRed[tid] += sRed[tid + s];
            __syncthreads();
        }
        if (tid == 0) {
            out[0] = sRed[0] * invT;
            g_count = 0;
        }
    }
}

extern "C" void kernel_launch(void* const* d_in, const int* in_sizes, int n_in,
                              void* d_out, int out_size) {
    const float* data  = (const float*)d_in[0];
    const float* wghts = (const float*)d_in[1];
    const float* means = (const float*)d_in[2];
    const float* dcovs = (const float*)d_in[3];
    float* out = (float*)d_out;

    const int T = in_sizes[0] / GMM_D;
    const int ntiles = (T + PPB - 1) / PPB;
    const int grid = (ntiles < NBLK) ? ntiles : NBLK;

    gmm_precompute<<<1, 1024>>>(wghts, means, dcovs);
    gmm_main<<<grid, TPB>>>(data, means, out, T, ntiles, 1.0f / (float)T);
}